// round 13
// baseline (speedup 1.0000x reference)
#include <cuda_runtime.h>
#include <cuda_fp16.h>
#include <math.h>

#define NN 50000
#define NF 128
#define DIM 10
#define NE 1600000
#define NG 1000
#define PD 12            // fp32 padded stride for xr

// ---------------- scratch ----------------
__device__ unsigned g_edgep[NE];    // packed (src:lo16, dst:hi16)
__device__ float  g_deginv[NN];
__device__ float4 g_xlh[NN * 2];    // xl rows fp16: 16 halfs (10 vals, [10]=1.0 count, [11]=0)
__device__ float4 g_agg1h[NN * 2];  // fp16 accumulators; lane 10 accumulates degree
__device__ float4 g_xr[NN * 3];     // fp32
__device__ float  g_t[NN];          // u . h  (layer-2 edge payload, scalar)
__device__ float  g_w[NN];          // v . h  (layer-2 self term, scalar)
__device__ float  g_acc2[NN];       // fp32 scalar accumulator (layer 2)
__device__ float  g_poolz[NG];      // scalar pool
__device__ int    g_cnt[NG];
__device__ float  g_u[DIM], g_v[DIM];
__device__ int    g_done;           // last-block ticket (reset every call)
__device__ int    g_ei32;
__device__ int    g_b32;

__device__ __forceinline__ void redf(float* p, float v) {
    asm volatile("red.global.add.f32 [%0], %1;" :: "l"(p), "f"(v) : "memory");
}
__device__ __forceinline__ void redh8(void* p, uint4 v) {      // 8 halfs, 16B
    asm volatile("red.global.add.noftz.v4.f16x2 [%0], {%1,%2,%3,%4};"
                 :: "l"(p), "r"(v.x), "r"(v.y), "r"(v.z), "r"(v.w) : "memory");
}
__device__ __forceinline__ void redh4(void* p, uint2 v) {      // 4 halfs, 8B
    asm volatile("red.global.add.noftz.v2.f16x2 [%0], {%1,%2};"
                 :: "l"(p), "r"(v.x), "r"(v.y) : "memory");
}

// ---------------- kernels ----------------
// Fused GEMV: xl = x@W1l^T (fp16 + count lane), xr = x@W1r^T (fp32).
// Block 0 additionally: dtype detect, u/v build, pool/cnt/done zero.
// Each block zeroes its own nodes' agg1h/acc2 slices.
__global__ __launch_bounds__(256) void gemv1(const float* __restrict__ x,
                                             const float* __restrict__ W1l,
                                             const float* __restrict__ W1r,
                                             const float* __restrict__ W2l,
                                             const float* __restrict__ W2r,
                                             const float* __restrict__ Wfc,
                                             const long long* __restrict__ ei,
                                             const long long* __restrict__ batch) {
    __shared__ __align__(16) float sW[20 * 128];
    __shared__ __align__(16) float sX[64 * 132];
    int t = threadIdx.x;
    int n0 = blockIdx.x * 64;
    if (blockIdx.x == 0) {       // init duties (consumed only by later kernels)
        for (int j = t; j < NG; j += 256) { g_poolz[j] = 0.f; g_cnt[j] = 0; }
        if (t == 255) g_done = 0;
        if (t < 10) {            // u_j = sum_d Wfc[d]*W2l[d][j]; v_j with W2r
            float u = 0.f, v = 0.f;
#pragma unroll
            for (int d = 0; d < 10; d++) {
                float f = Wfc[d];
                u += f * W2l[d * 10 + t];
                v += f * W2r[d * 10 + t];
            }
            g_u[t] = u; g_v[t] = v;
        }
        if (t == 32) {
            int f = 0;
            for (int k = 0; k < 64; k++) {
                long long v = ei[k];
                if (v < 0 || v >= NN) f = 1;
            }
            g_ei32 = f;
        }
        if (t == 64) {
            int fb = 0;
            for (int k = 0; k < 64; k++) {
                long long v = batch[12000 + k];
                if (v < 0 || v >= NG) fb = 1;
            }
            g_b32 = fb;
        }
    }
    // zero accumulator slices for this block's nodes
    {
        float4 z = make_float4(0.f, 0.f, 0.f, 0.f);
        for (int i = t; i < 128; i += 256) {
            int node = n0 + (i >> 1);
            if (node < NN) g_agg1h[node * 2 + (i & 1)] = z;
        }
        for (int i = t; i < 64; i += 256) {
            int node = n0 + i;
            if (node < NN) g_acc2[node] = 0.f;
        }
    }
    for (int i = t; i < 20 * 128; i += 256) {
        int d = i >> 7, k = i & 127;
        sW[i] = (d < 10) ? W1l[d * 128 + k] : W1r[(d - 10) * 128 + k];
    }
    for (int i = t; i < 64 * 32; i += 256) {
        int n = i >> 5, k4 = i & 31;
        int node = n0 + n;
        float4 v = (node < NN) ? ((const float4*)x)[node * 32 + k4]
                               : make_float4(0.f, 0.f, 0.f, 0.f);
        *(float4*)&sX[n * 132 + k4 * 4] = v;
    }
    __syncthreads();
    int n = t & 63, g = t >> 6;
    int node = n0 + n;
    float acc[5] = {0.f, 0.f, 0.f, 0.f, 0.f};
    const float4* xr4 = (const float4*)&sX[n * 132];
    const float4* w4  = (const float4*)sW;
#pragma unroll
    for (int k4 = 0; k4 < 32; k4++) {
        float4 xv = xr4[k4];
#pragma unroll
        for (int j = 0; j < 5; j++) {
            float4 w = w4[(g * 5 + j) * 32 + k4];
            acc[j] += xv.x * w.x + xv.y * w.y + xv.z * w.z + xv.w * w.w;
        }
    }
    if (node < NN) {
        __half* xlh = (__half*)g_xlh;
#pragma unroll
        for (int j = 0; j < 5; j++) {
            int d = g * 5 + j;
            if (d < 10) xlh[node * 16 + d] = __float2half(acc[j]);
            else        ((float*)g_xr)[node * PD + (d - 10)] = acc[j];
        }
        if (g == 1) {   // count lane + zero pad (lanes 10,11)
            *(__half2*)&xlh[node * 16 + 10] = __halves2half2(__float2half(1.0f), __float2half(0.0f));
        }
    }
}

// Layer-1 edge pass, 4 edges/thread: vector ei loads, uint4 packed store
// (src/dst as uint16), 2 RMW transactions per edge (16B + 8B fp16 REDs).
__global__ __launch_bounds__(256) void edge_agg1(const long long* __restrict__ ei) {
    int t = blockIdx.x * blockDim.x + threadIdx.x;
    int e0 = t * 4;
    if (e0 >= NE) return;          // NE % 4 == 0: always full quads
    int s[4], d[4];
    if (g_ei32) {
        const int* e32 = (const int*)ei;
        int4 ss = ((const int4*)e32)[t];
        int4 dd = ((const int4*)(e32 + NE))[t];
        s[0] = ss.x; s[1] = ss.y; s[2] = ss.z; s[3] = ss.w;
        d[0] = dd.x; d[1] = dd.y; d[2] = dd.z; d[3] = dd.w;
    } else {
        longlong2 sa = ((const longlong2*)ei)[t * 2];
        longlong2 sb = ((const longlong2*)ei)[t * 2 + 1];
        longlong2 da = ((const longlong2*)(ei + NE))[t * 2];
        longlong2 db = ((const longlong2*)(ei + NE))[t * 2 + 1];
        s[0] = (int)sa.x; s[1] = (int)sa.y; s[2] = (int)sb.x; s[3] = (int)sb.y;
        d[0] = (int)da.x; d[1] = (int)da.y; d[2] = (int)db.x; d[3] = (int)db.y;
    }
    uint4 pk;
    pk.x = (unsigned)s[0] | ((unsigned)d[0] << 16);
    pk.y = (unsigned)s[1] | ((unsigned)d[1] << 16);
    pk.z = (unsigned)s[2] | ((unsigned)d[2] << 16);
    pk.w = (unsigned)s[3] | ((unsigned)d[3] << 16);
    *(uint4*)&g_edgep[e0] = pk;
#pragma unroll
    for (int i = 0; i < 4; i++) {
        uint4 u0 = *((const uint4*)g_xlh + s[i] * 2);
        uint2 u1 = ((const uint2*)g_xlh)[s[i] * 4 + 2];
        char* r = (char*)g_agg1h + (size_t)d[i] * 32;
        redh8(r, u0);
        redh4(r + 16, u1);
    }
}

// deg from count lane; h = relu(agg1/deg + xr); t = u.h; w = v.h.
__global__ __launch_bounds__(256) void combine1() {
    __shared__ float su[10], sv[10];
    int t = threadIdx.x;
    if (t < 10) { su[t] = g_u[t]; sv[t] = g_v[t]; }
    __syncthreads();
    int n = blockIdx.x * blockDim.x + t;
    if (n >= NN) return;
    uint4 a0 = *((const uint4*)g_agg1h + n * 2);
    uint2 a1 = ((const uint2*)g_agg1h)[n * 4 + 2];
    float ag[10];
    float2 p;
    p = __half22float2(*(__half2*)&a0.x); ag[0] = p.x; ag[1] = p.y;
    p = __half22float2(*(__half2*)&a0.y); ag[2] = p.x; ag[3] = p.y;
    p = __half22float2(*(__half2*)&a0.z); ag[4] = p.x; ag[5] = p.y;
    p = __half22float2(*(__half2*)&a0.w); ag[6] = p.x; ag[7] = p.y;
    p = __half22float2(*(__half2*)&a1.x); ag[8] = p.x; ag[9] = p.y;
    p = __half22float2(*(__half2*)&a1.y);          // p.x = degree (fp16-exact int)
    float di = 1.0f / fmaxf(p.x, 1.0f);
    g_deginv[n] = di;
    const float4* xr4 = (const float4*)((const float*)g_xr + n * PD);
    float4 x0 = xr4[0], x1 = xr4[1], x2 = xr4[2];
    float xr[10] = {x0.x, x0.y, x0.z, x0.w, x1.x, x1.y, x1.z, x1.w, x2.x, x2.y};
    float tv = 0.f, wv = 0.f;
#pragma unroll
    for (int d = 0; d < 10; d++) {
        float h = fmaxf(ag[d] * di + xr[d], 0.f);
        tv += su[d] * h;
        wv += sv[d] * h;
    }
    g_t[n] = tv;
    g_w[n] = wv;
}

// Layer-2 edge pass: ONE scalar fp32 RED per edge; 4 edges/thread, 16B edge load.
__global__ __launch_bounds__(256) void edge_agg2() {
    int t = blockIdx.x * blockDim.x + threadIdx.x;
    int e0 = t * 4;
    if (e0 >= NE) return;
    uint4 pk = *(const uint4*)&g_edgep[e0];
    float t0 = g_t[pk.x & 0xffff];
    float t1 = g_t[pk.y & 0xffff];
    float t2 = g_t[pk.z & 0xffff];
    float t3 = g_t[pk.w & 0xffff];
    redf(&g_acc2[pk.x >> 16], t0);
    redf(&g_acc2[pk.y >> 16], t1);
    redf(&g_acc2[pk.z >> 16], t2);
    redf(&g_acc2[pk.w >> 16], t3);
}

// val = deg_inv*acc2 + w; pool[batch] += val; count; last block writes output.
__global__ __launch_bounds__(256) void combine2_pool(const long long* __restrict__ batch,
                                                     float* __restrict__ out) {
    int n = blockIdx.x * blockDim.x + threadIdx.x;
    if (n < NN) {
        float val = g_deginv[n] * g_acc2[n] + g_w[n];
        int b = g_b32 ? ((const int*)batch)[n] : (int)batch[n];
        redf(&g_poolz[b], val);
        atomicAdd(&g_cnt[b], 1);
    }
    __threadfence();
    __shared__ int last;
    if (threadIdx.x == 0)
        last = (atomicAdd(&g_done, 1) == (int)gridDim.x - 1);
    __syncthreads();
    if (last) {
        __threadfence();
        for (int g = threadIdx.x; g < NG; g += blockDim.x) {
            float c = fmaxf((float)g_cnt[g], 1.0f);
            float z = g_poolz[g] / c;
            out[g] = 1.0f / (1.0f + expf(-z));
        }
    }
}

// ---------------- launch ----------------
extern "C" void kernel_launch(void* const* d_in, const int* in_sizes, int n_in,
                              void* d_out, int out_size) {
    const float *x = 0, *W1l = 0, *W1r = 0, *W2l = 0, *W2r = 0, *Wfc = 0;
    const long long *ei = 0, *batch = 0;
    for (int i = 0; i < n_in; i++) {
        int sz = in_sizes[i];
        if (sz == NN * NF)        x = (const float*)d_in[i];
        else if (sz == DIM * NF)  { if (!W1l) W1l = (const float*)d_in[i]; else W1r = (const float*)d_in[i]; }
        else if (sz == DIM * DIM) { if (!W2l) W2l = (const float*)d_in[i]; else W2r = (const float*)d_in[i]; }
        else if (sz == DIM)       Wfc = (const float*)d_in[i];
        else if (sz == 2 * NE)    ei = (const long long*)d_in[i];
        else if (sz == NN)        batch = (const long long*)d_in[i];
    }
    float* out = (float*)d_out;

    const int TB = 256;
    gemv1<<<(NN + 63) / 64, TB>>>(x, W1l, W1r, W2l, W2r, Wfc, ei, batch);
    edge_agg1<<<(NE / 4 + TB - 1) / TB, TB>>>(ei);
    combine1<<<(NN + TB - 1) / TB, TB>>>();
    edge_agg2<<<(NE / 4 + TB - 1) / TB, TB>>>();
    combine2_pool<<<(NN + TB - 1) / TB, TB>>>(batch, out);
}

// round 14
// speedup vs baseline: 1.4243x; 1.4243x over previous
#include <cuda_runtime.h>
#include <cuda_fp16.h>
#include <math.h>

#define NN 50000
#define NF 128
#define DIM 10
#define NE 1600000
#define NG 1000
#define PD 12            // fp32 padded stride for xr

// ---------------- scratch ----------------
__device__ int2   g_edge[NE];       // (src, dst) packed in pass 0, reused pass 1
__device__ float  g_deginv[NN];
__device__ float4 g_xlh[NN * 2];    // xl rows fp16: 16 halfs (10 vals, [10]=1.0 count, [11]=0)
__device__ float4 g_agg1h[NN * 2];  // fp16 accumulators; lane 10 accumulates degree
__device__ float4 g_xr[NN * 3];     // fp32
__device__ float  g_t[NN];          // u . h  (layer-2 edge payload, scalar)
__device__ float  g_w[NN];          // v . h  (layer-2 self term, scalar)
__device__ float  g_acc2[NN];       // fp32 scalar accumulator (layer 2)
__device__ float  g_poolz[NG];      // scalar pool
__device__ int    g_cnt[NG];
__device__ float  g_u[DIM], g_v[DIM];
__device__ int    g_done;           // last-block ticket (reset every call)
__device__ int    g_ei32;
__device__ int    g_b32;

__device__ __forceinline__ void redf(float* p, float v) {
    asm volatile("red.global.add.f32 [%0], %1;" :: "l"(p), "f"(v) : "memory");
}
__device__ __forceinline__ void redh8(void* p, uint4 v) {      // 8 halfs, 16B
    asm volatile("red.global.add.noftz.v4.f16x2 [%0], {%1,%2,%3,%4};"
                 :: "l"(p), "r"(v.x), "r"(v.y), "r"(v.z), "r"(v.w) : "memory");
}
__device__ __forceinline__ void redh4(void* p, uint2 v) {      // 4 halfs, 8B
    asm volatile("red.global.add.noftz.v2.f16x2 [%0], {%1,%2};"
                 :: "l"(p), "r"(v.x), "r"(v.y) : "memory");
}

// ---------------- kernels ----------------
// ONE block: dtype detect (warp-parallel), u/v build, zero pool/cnt/done.
__global__ void init_small(const long long* ei, const long long* batch,
                           const float* W2l, const float* W2r, const float* Wfc) {
    int i = threadIdx.x;
    for (int j = i; j < NG; j += 256) { g_poolz[j] = 0.f; g_cnt[j] = 0; }
    if (i == 255) g_done = 0;
    if (i < 10) {   // u_j = sum_d Wfc[d]*W2l[d][j]; v_j likewise with W2r
        float u = 0.f, v = 0.f;
#pragma unroll
        for (int d = 0; d < 10; d++) {
            float f = Wfc[d];
            u += f * W2l[d * 10 + i];
            v += f * W2r[d * 10 + i];
        }
        g_u[i] = u; g_v[i] = v;
    }
    // warp-parallel dtype detection: warps 4-5 (threads 128..191) check ei,
    // warps 6-7 (threads 192..255) check batch. 64 parallel loads each.
    if (i >= 128 && i < 192) {
        long long v = ei[i - 128];
        unsigned bad = __ballot_sync(0xffffffffu, v < 0 || v >= NN);
        if ((i & 31) == 0) {
            if (bad) g_ei32 = 1;
            else if (i == 128) g_ei32 = 0;   // only set 0 once (both warps clean)
        }
    }
    if (i >= 192) {
        long long v = batch[12000 + (i - 192)];
        unsigned bad = __ballot_sync(0xffffffffu, v < 0 || v >= NG);
        if ((i & 31) == 0) {
            if (bad) g_b32 = 1;
            else if (i == 192) g_b32 = 0;
        }
    }
}

// Fused GEMV: xl = x@W1l^T (fp16 into g_xlh, +count lane), xr = x@W1r^T (fp32).
// Also zeroes this block's slice of g_agg1h / g_acc2 (no separate init pass).
__global__ __launch_bounds__(256) void gemv1(const float* __restrict__ x,
                                             const float* __restrict__ W1l,
                                             const float* __restrict__ W1r) {
    __shared__ __align__(16) float sW[20 * 128];
    __shared__ __align__(16) float sX[64 * 132];
    int t = threadIdx.x;
    int n0 = blockIdx.x * 64;
    // zero accumulator slices for this block's nodes
    {
        float4 z = make_float4(0.f, 0.f, 0.f, 0.f);
        for (int i = t; i < 128; i += 256) {
            int node = n0 + (i >> 1);
            if (node < NN) g_agg1h[node * 2 + (i & 1)] = z;
        }
        for (int i = t; i < 64; i += 256) {
            int node = n0 + i;
            if (node < NN) g_acc2[node] = 0.f;
        }
    }
    for (int i = t; i < 20 * 128; i += 256) {
        int d = i >> 7, k = i & 127;
        sW[i] = (d < 10) ? W1l[d * 128 + k] : W1r[(d - 10) * 128 + k];
    }
    for (int i = t; i < 64 * 32; i += 256) {
        int n = i >> 5, k4 = i & 31;
        int node = n0 + n;
        float4 v = (node < NN) ? ((const float4*)x)[node * 32 + k4]
                               : make_float4(0.f, 0.f, 0.f, 0.f);
        *(float4*)&sX[n * 132 + k4 * 4] = v;
    }
    __syncthreads();
    int n = t & 63, g = t >> 6;
    int node = n0 + n;
    float acc[5] = {0.f, 0.f, 0.f, 0.f, 0.f};
    const float4* xr4 = (const float4*)&sX[n * 132];
    const float4* w4  = (const float4*)sW;
#pragma unroll
    for (int k4 = 0; k4 < 32; k4++) {
        float4 xv = xr4[k4];
#pragma unroll
        for (int j = 0; j < 5; j++) {
            float4 w = w4[(g * 5 + j) * 32 + k4];
            acc[j] += xv.x * w.x + xv.y * w.y + xv.z * w.z + xv.w * w.w;
        }
    }
    if (node < NN) {
        __half* xlh = (__half*)g_xlh;
#pragma unroll
        for (int j = 0; j < 5; j++) {
            int d = g * 5 + j;
            if (d < 10) xlh[node * 16 + d] = __float2half(acc[j]);
            else        ((float*)g_xr)[node * PD + (d - 10)] = acc[j];
        }
        if (g == 1) {   // count lane + zero pad (lanes 10,11)
            *(__half2*)&xlh[node * 16 + 10] = __halves2half2(__float2half(1.0f), __float2half(0.0f));
        }
    }
}

// Layer-1 edge pass, 2 edges/thread: vector ei loads, int4 pack store,
// 2 RMW transactions per edge (16B dims0-7 + 8B dims8-9/count/pad).
__global__ __launch_bounds__(256) void edge_agg1(const long long* __restrict__ ei) {
    int t = blockIdx.x * blockDim.x + threadIdx.x;
    int e0 = t * 2;
    if (e0 >= NE) return;          // NE even: always full pairs
    int s0, s1, d0, d1;
    if (g_ei32) {
        const int* e32 = (const int*)ei;
        int2 ss = ((const int2*)e32)[t];
        int2 dd = ((const int2*)(e32 + NE))[t];
        s0 = ss.x; s1 = ss.y; d0 = dd.x; d1 = dd.y;
    } else {
        longlong2 ss = ((const longlong2*)ei)[t];
        longlong2 dd = ((const longlong2*)(ei + NE))[t];
        s0 = (int)ss.x; s1 = (int)ss.y; d0 = (int)dd.x; d1 = (int)dd.y;
    }
    *(int4*)&g_edge[e0] = make_int4(s0, d0, s1, d1);
    uint4 u0 = *((const uint4*)g_xlh + s0 * 2);
    uint2 u1 = ((const uint2*)g_xlh)[s0 * 4 + 2];
    uint4 v0 = *((const uint4*)g_xlh + s1 * 2);
    uint2 v1 = ((const uint2*)g_xlh)[s1 * 4 + 2];
    char* r0 = (char*)g_agg1h + (size_t)d0 * 32;
    char* r1 = (char*)g_agg1h + (size_t)d1 * 32;
    redh8(r0, u0);
    redh4(r0 + 16, u1);
    redh8(r1, v0);
    redh4(r1 + 16, v1);
}

// deg from count lane; h = relu(agg1/deg + xr); t = u.h; w = v.h.
__global__ __launch_bounds__(256) void combine1() {
    __shared__ float su[10], sv[10];
    int t = threadIdx.x;
    if (t < 10) { su[t] = g_u[t]; sv[t] = g_v[t]; }
    __syncthreads();
    int n = blockIdx.x * blockDim.x + t;
    if (n >= NN) return;
    uint4 a0 = *((const uint4*)g_agg1h + n * 2);
    uint2 a1 = ((const uint2*)g_agg1h)[n * 4 + 2];
    float ag[10];
    float2 p;
    p = __half22float2(*(__half2*)&a0.x); ag[0] = p.x; ag[1] = p.y;
    p = __half22float2(*(__half2*)&a0.y); ag[2] = p.x; ag[3] = p.y;
    p = __half22float2(*(__half2*)&a0.z); ag[4] = p.x; ag[5] = p.y;
    p = __half22float2(*(__half2*)&a0.w); ag[6] = p.x; ag[7] = p.y;
    p = __half22float2(*(__half2*)&a1.x); ag[8] = p.x; ag[9] = p.y;
    p = __half22float2(*(__half2*)&a1.y);          // p.x = degree (fp16-exact int)
    float di = 1.0f / fmaxf(p.x, 1.0f);
    g_deginv[n] = di;
    const float4* xr4 = (const float4*)((const float*)g_xr + n * PD);
    float4 x0 = xr4[0], x1 = xr4[1], x2 = xr4[2];
    float xr[10] = {x0.x, x0.y, x0.z, x0.w, x1.x, x1.y, x1.z, x1.w, x2.x, x2.y};
    float tv = 0.f, wv = 0.f;
#pragma unroll
    for (int d = 0; d < 10; d++) {
        float h = fmaxf(ag[d] * di + xr[d], 0.f);
        tv += su[d] * h;
        wv += sv[d] * h;
    }
    g_t[n] = tv;
    g_w[n] = wv;
}

// Layer-2 edge pass: ONE scalar fp32 RED per edge; 4 edges/thread.
__global__ __launch_bounds__(256) void edge_agg2() {
    int t = blockIdx.x * blockDim.x + threadIdx.x;
    int e0 = t * 4;
    if (e0 >= NE) return;          // NE % 4 == 0: always full quads
    int4 p = *(const int4*)&g_edge[e0];
    int4 q = *(const int4*)&g_edge[e0 + 2];
    float t0 = g_t[p.x], t1 = g_t[p.z], t2 = g_t[q.x], t3 = g_t[q.z];
    redf(&g_acc2[p.y], t0);
    redf(&g_acc2[p.w], t1);
    redf(&g_acc2[q.y], t2);
    redf(&g_acc2[q.w], t3);
}

// val = deg_inv*acc2 + w; pool[batch] += val; count; last block writes output.
__global__ __launch_bounds__(256) void combine2_pool(const long long* __restrict__ batch,
                                                     float* __restrict__ out) {
    int n = blockIdx.x * blockDim.x + threadIdx.x;
    if (n < NN) {
        float val = g_deginv[n] * g_acc2[n] + g_w[n];
        int b = g_b32 ? ((const int*)batch)[n] : (int)batch[n];
        redf(&g_poolz[b], val);
        atomicAdd(&g_cnt[b], 1);
    }
    __threadfence();
    __shared__ int last;
    if (threadIdx.x == 0)
        last = (atomicAdd(&g_done, 1) == (int)gridDim.x - 1);
    __syncthreads();
    if (last) {
        __threadfence();
        for (int g = threadIdx.x; g < NG; g += blockDim.x) {
            float c = fmaxf((float)g_cnt[g], 1.0f);
            float z = g_poolz[g] / c;
            out[g] = 1.0f / (1.0f + expf(-z));
        }
    }
}

// ---------------- launch ----------------
extern "C" void kernel_launch(void* const* d_in, const int* in_sizes, int n_in,
                              void* d_out, int out_size) {
    const float *x = 0, *W1l = 0, *W1r = 0, *W2l = 0, *W2r = 0, *Wfc = 0;
    const long long *ei = 0, *batch = 0;
    for (int i = 0; i < n_in; i++) {
        int sz = in_sizes[i];
        if (sz == NN * NF)        x = (const float*)d_in[i];
        else if (sz == DIM * NF)  { if (!W1l) W1l = (const float*)d_in[i]; else W1r = (const float*)d_in[i]; }
        else if (sz == DIM * DIM) { if (!W2l) W2l = (const float*)d_in[i]; else W2r = (const float*)d_in[i]; }
        else if (sz == DIM)       Wfc = (const float*)d_in[i];
        else if (sz == 2 * NE)    ei = (const long long*)d_in[i];
        else if (sz == NN)        batch = (const long long*)d_in[i];
    }
    float* out = (float*)d_out;

    const int TB = 256;
    init_small<<<1, TB>>>(ei, batch, W2l, W2r, Wfc);
    gemv1<<<(NN + 63) / 64, TB>>>(x, W1l, W1r);
    edge_agg1<<<(NE / 2 + TB - 1) / TB, TB>>>(ei);
    combine1<<<(NN + TB - 1) / TB, TB>>>();
    edge_agg2<<<(NE / 4 + TB - 1) / TB, TB>>>();
    combine2_pool<<<(NN + TB - 1) / TB, TB>>>(batch, out);
}

// round 15
// speedup vs baseline: 1.4362x; 1.0084x over previous
#include <cuda_runtime.h>
#include <cuda_fp16.h>
#include <math.h>

#define NN 50000
#define NF 128
#define DIM 10
#define NE 1600000
#define NG 1000
#define PD 12            // fp32 padded stride for xr

// ---------------- scratch ----------------
__device__ int2   g_edge[NE];       // (src, dst) packed in pass 0, reused pass 1
__device__ float  g_deginv[NN];
__device__ float4 g_xlh[NN * 2];    // xl rows fp16: 16 halfs (10 vals, [10]=1.0 count, [11]=0)
__device__ float4 g_agg1h[NN * 2];  // fp16 accumulators; lane 10 accumulates degree
__device__ float4 g_xr[NN * 3];     // fp32
__device__ float  g_t[NN];          // u . h  (layer-2 edge payload, scalar)
__device__ float  g_w[NN];          // v . h  (layer-2 self term, scalar)
__device__ float  g_acc2[NN];       // fp32 scalar accumulator (layer 2)
__device__ float  g_poolz[NG];      // scalar pool
__device__ int    g_cnt[NG];
__device__ float  g_u[DIM], g_v[DIM];
__device__ int    g_done;           // last-block ticket (reset every call)
__device__ int    g_ei32;
__device__ int    g_b32;

__device__ __forceinline__ void redf(float* p, float v) {
    asm volatile("red.global.add.f32 [%0], %1;" :: "l"(p), "f"(v) : "memory");
}
__device__ __forceinline__ void redh8(void* p, uint4 v) {      // 8 halfs, 16B
    asm volatile("red.global.add.noftz.v4.f16x2 [%0], {%1,%2,%3,%4};"
                 :: "l"(p), "r"(v.x), "r"(v.y), "r"(v.z), "r"(v.w) : "memory");
}
__device__ __forceinline__ void redh4(void* p, uint2 v) {      // 4 halfs, 8B
    asm volatile("red.global.add.noftz.v2.f16x2 [%0], {%1,%2};"
                 :: "l"(p), "r"(v.x), "r"(v.y) : "memory");
}

// ---------------- kernels ----------------
// Fused GEMV: xl = x@W1l^T (fp16 + count lane), xr = x@W1r^T (fp32).
// Each block zeroes its own nodes' agg1h/acc2 slices.
// Block 0 additionally (consumed only by LATER kernels — no intra-kernel race):
//   pool/cnt/done zero, u/v build, warp-parallel dtype detect.
__global__ __launch_bounds__(256) void gemv1(const float* __restrict__ x,
                                             const float* __restrict__ W1l,
                                             const float* __restrict__ W1r,
                                             const float* __restrict__ W2l,
                                             const float* __restrict__ W2r,
                                             const float* __restrict__ Wfc,
                                             const long long* __restrict__ ei,
                                             const long long* __restrict__ batch) {
    __shared__ __align__(16) float sW[20 * 128];
    __shared__ __align__(16) float sX[64 * 132];
    int t = threadIdx.x;
    int n0 = blockIdx.x * 64;
    if (blockIdx.x == 0) {
        for (int j = t; j < NG; j += 256) { g_poolz[j] = 0.f; g_cnt[j] = 0; }
        if (t == 255) g_done = 0;
        if (t < 10) {            // u_j = sum_d Wfc[d]*W2l[d][j]; v_j with W2r
            float u = 0.f, v = 0.f;
#pragma unroll
            for (int d = 0; d < 10; d++) {
                float f = Wfc[d];
                u += f * W2l[d * 10 + t];
                v += f * W2r[d * 10 + t];
            }
            g_u[t] = u; g_v[t] = v;
        }
        // warp-parallel dtype detect: warps 4-5 check ei, warps 6-7 check batch.
        if (t >= 128 && t < 192) {
            long long v = ei[t - 128];
            unsigned bad = __ballot_sync(0xffffffffu, v < 0 || v >= NN);
            if ((t & 31) == 0) {
                if (bad) g_ei32 = 1;
                else if (t == 128) g_ei32 = 0;
            }
        }
        if (t >= 192) {
            long long v = batch[12000 + (t - 192)];
            unsigned bad = __ballot_sync(0xffffffffu, v < 0 || v >= NG);
            if ((t & 31) == 0) {
                if (bad) g_b32 = 1;
                else if (t == 192) g_b32 = 0;
            }
        }
    }
    // zero accumulator slices for this block's nodes
    {
        float4 z = make_float4(0.f, 0.f, 0.f, 0.f);
        for (int i = t; i < 128; i += 256) {
            int node = n0 + (i >> 1);
            if (node < NN) g_agg1h[node * 2 + (i & 1)] = z;
        }
        for (int i = t; i < 64; i += 256) {
            int node = n0 + i;
            if (node < NN) g_acc2[node] = 0.f;
        }
    }
    for (int i = t; i < 20 * 128; i += 256) {
        int d = i >> 7, k = i & 127;
        sW[i] = (d < 10) ? W1l[d * 128 + k] : W1r[(d - 10) * 128 + k];
    }
    for (int i = t; i < 64 * 32; i += 256) {
        int n = i >> 5, k4 = i & 31;
        int node = n0 + n;
        float4 v = (node < NN) ? ((const float4*)x)[node * 32 + k4]
                               : make_float4(0.f, 0.f, 0.f, 0.f);
        *(float4*)&sX[n * 132 + k4 * 4] = v;
    }
    __syncthreads();
    int n = t & 63, g = t >> 6;
    int node = n0 + n;
    float acc[5] = {0.f, 0.f, 0.f, 0.f, 0.f};
    const float4* xr4 = (const float4*)&sX[n * 132];
    const float4* w4  = (const float4*)sW;
#pragma unroll
    for (int k4 = 0; k4 < 32; k4++) {
        float4 xv = xr4[k4];
#pragma unroll
        for (int j = 0; j < 5; j++) {
            float4 w = w4[(g * 5 + j) * 32 + k4];
            acc[j] += xv.x * w.x + xv.y * w.y + xv.z * w.z + xv.w * w.w;
        }
    }
    if (node < NN) {
        __half* xlh = (__half*)g_xlh;
#pragma unroll
        for (int j = 0; j < 5; j++) {
            int d = g * 5 + j;
            if (d < 10) xlh[node * 16 + d] = __float2half(acc[j]);
            else        ((float*)g_xr)[node * PD + (d - 10)] = acc[j];
        }
        if (g == 1) {   // count lane + zero pad (lanes 10,11)
            *(__half2*)&xlh[node * 16 + 10] = __halves2half2(__float2half(1.0f), __float2half(0.0f));
        }
    }
}

// Layer-1 edge pass, 2 edges/thread: vector ei loads, int4 pack store,
// 2 RMW transactions per edge (16B dims0-7 + 8B dims8-9/count/pad).
__global__ __launch_bounds__(256) void edge_agg1(const long long* __restrict__ ei) {
    int t = blockIdx.x * blockDim.x + threadIdx.x;
    int e0 = t * 2;
    if (e0 >= NE) return;          // NE even: always full pairs
    int s0, s1, d0, d1;
    if (g_ei32) {
        const int* e32 = (const int*)ei;
        int2 ss = ((const int2*)e32)[t];
        int2 dd = ((const int2*)(e32 + NE))[t];
        s0 = ss.x; s1 = ss.y; d0 = dd.x; d1 = dd.y;
    } else {
        longlong2 ss = ((const longlong2*)ei)[t];
        longlong2 dd = ((const longlong2*)(ei + NE))[t];
        s0 = (int)ss.x; s1 = (int)ss.y; d0 = (int)dd.x; d1 = (int)dd.y;
    }
    *(int4*)&g_edge[e0] = make_int4(s0, d0, s1, d1);
    uint4 u0 = *((const uint4*)g_xlh + s0 * 2);
    uint2 u1 = ((const uint2*)g_xlh)[s0 * 4 + 2];
    uint4 v0 = *((const uint4*)g_xlh + s1 * 2);
    uint2 v1 = ((const uint2*)g_xlh)[s1 * 4 + 2];
    char* r0 = (char*)g_agg1h + (size_t)d0 * 32;
    char* r1 = (char*)g_agg1h + (size_t)d1 * 32;
    redh8(r0, u0);
    redh4(r0 + 16, u1);
    redh8(r1, v0);
    redh4(r1 + 16, v1);
}

// deg from count lane; h = relu(agg1/deg + xr); t = u.h; w = v.h.
__global__ __launch_bounds__(256) void combine1() {
    __shared__ float su[10], sv[10];
    int t = threadIdx.x;
    if (t < 10) { su[t] = g_u[t]; sv[t] = g_v[t]; }
    __syncthreads();
    int n = blockIdx.x * blockDim.x + t;
    if (n >= NN) return;
    uint4 a0 = *((const uint4*)g_agg1h + n * 2);
    uint2 a1 = ((const uint2*)g_agg1h)[n * 4 + 2];
    float ag[10];
    float2 p;
    p = __half22float2(*(__half2*)&a0.x); ag[0] = p.x; ag[1] = p.y;
    p = __half22float2(*(__half2*)&a0.y); ag[2] = p.x; ag[3] = p.y;
    p = __half22float2(*(__half2*)&a0.z); ag[4] = p.x; ag[5] = p.y;
    p = __half22float2(*(__half2*)&a0.w); ag[6] = p.x; ag[7] = p.y;
    p = __half22float2(*(__half2*)&a1.x); ag[8] = p.x; ag[9] = p.y;
    p = __half22float2(*(__half2*)&a1.y);          // p.x = degree (fp16-exact int)
    float di = 1.0f / fmaxf(p.x, 1.0f);
    g_deginv[n] = di;
    const float4* xr4 = (const float4*)((const float*)g_xr + n * PD);
    float4 x0 = xr4[0], x1 = xr4[1], x2 = xr4[2];
    float xr[10] = {x0.x, x0.y, x0.z, x0.w, x1.x, x1.y, x1.z, x1.w, x2.x, x2.y};
    float tv = 0.f, wv = 0.f;
#pragma unroll
    for (int d = 0; d < 10; d++) {
        float h = fmaxf(ag[d] * di + xr[d], 0.f);
        tv += su[d] * h;
        wv += sv[d] * h;
    }
    g_t[n] = tv;
    g_w[n] = wv;
}

// Layer-2 edge pass: ONE scalar fp32 RED per edge; 4 edges/thread.
__global__ __launch_bounds__(256) void edge_agg2() {
    int t = blockIdx.x * blockDim.x + threadIdx.x;
    int e0 = t * 4;
    if (e0 >= NE) return;          // NE % 4 == 0: always full quads
    int4 p = *(const int4*)&g_edge[e0];
    int4 q = *(const int4*)&g_edge[e0 + 2];
    float t0 = g_t[p.x], t1 = g_t[p.z], t2 = g_t[q.x], t3 = g_t[q.z];
    redf(&g_acc2[p.y], t0);
    redf(&g_acc2[p.w], t1);
    redf(&g_acc2[q.y], t2);
    redf(&g_acc2[q.w], t3);
}

// val = deg_inv*acc2 + w; pool[batch] += val; count; last block writes output.
__global__ __launch_bounds__(256) void combine2_pool(const long long* __restrict__ batch,
                                                     float* __restrict__ out) {
    int n = blockIdx.x * blockDim.x + threadIdx.x;
    if (n < NN) {
        float val = g_deginv[n] * g_acc2[n] + g_w[n];
        int b = g_b32 ? ((const int*)batch)[n] : (int)batch[n];
        redf(&g_poolz[b], val);
        atomicAdd(&g_cnt[b], 1);
    }
    __threadfence();
    __shared__ int last;
    if (threadIdx.x == 0)
        last = (atomicAdd(&g_done, 1) == (int)gridDim.x - 1);
    __syncthreads();
    if (last) {
        __threadfence();
        for (int g = threadIdx.x; g < NG; g += blockDim.x) {
            float c = fmaxf((float)g_cnt[g], 1.0f);
            float z = g_poolz[g] / c;
            out[g] = 1.0f / (1.0f + expf(-z));
        }
    }
}

// ---------------- launch ----------------
extern "C" void kernel_launch(void* const* d_in, const int* in_sizes, int n_in,
                              void* d_out, int out_size) {
    const float *x = 0, *W1l = 0, *W1r = 0, *W2l = 0, *W2r = 0, *Wfc = 0;
    const long long *ei = 0, *batch = 0;
    for (int i = 0; i < n_in; i++) {
        int sz = in_sizes[i];
        if (sz == NN * NF)        x = (const float*)d_in[i];
        else if (sz == DIM * NF)  { if (!W1l) W1l = (const float*)d_in[i]; else W1r = (const float*)d_in[i]; }
        else if (sz == DIM * DIM) { if (!W2l) W2l = (const float*)d_in[i]; else W2r = (const float*)d_in[i]; }
        else if (sz == DIM)       Wfc = (const float*)d_in[i];
        else if (sz == 2 * NE)    ei = (const long long*)d_in[i];
        else if (sz == NN)        batch = (const long long*)d_in[i];
    }
    float* out = (float*)d_out;

    const int TB = 256;
    gemv1<<<(NN + 63) / 64, TB>>>(x, W1l, W1r, W2l, W2r, Wfc, ei, batch);
    edge_agg1<<<(NE / 2 + TB - 1) / TB, TB>>>(ei);
    combine1<<<(NN + TB - 1) / TB, TB>>>();
    edge_agg2<<<(NE / 4 + TB - 1) / TB, TB>>>();
    combine2_pool<<<(NN + TB - 1) / TB, TB>>>(batch, out);
}